// round 3
// baseline (speedup 1.0000x reference)
#include <cuda_runtime.h>
#include <math.h>

// Problem constants
#define BB 2
#define SS 1024
#define HID 2048
#define NH 32
#define NKV 8
#define HD 64
#define GROUP 4

#define OUT_ELEMS   (BB * SS * HID)            // 4,194,304
#define ATTN_ELEMS  ((size_t)BB * NH * SS * SS) // 67,108,864

// Scratch (device globals: no runtime allocation allowed)
__device__ float g_q[(size_t)BB * NH * SS * HD];     // (b,h,s,d)
__device__ float g_k[(size_t)BB * NKV * SS * HD];    // (b,kv,s,d)
__device__ float g_v[(size_t)BB * NKV * SS * HD];
__device__ float g_ctx[(size_t)BB * SS * NH * HD];   // (b,s,h*d)
__device__ float g_attn_fallback[ATTN_ELEMS];        // used only if harness checks out only

// ---------------------------------------------------------------------------
// SGEMM: C = A[MxK] @ W[KxN], row-major, 128x128 tile, BK=8, 256 thr, 8x8/thr.
// mode 0: C[m*N+n]
// mode 1: head-split write: out[((b*nh + n/64)*S + s)*64 + n%64], b=m/S, s=m%S
// Requires M%128==0, N%128==0, K%8==0 (true for all uses here).
// ---------------------------------------------------------------------------
__global__ __launch_bounds__(256, 2)
void sgemm128(const float* __restrict__ A, const float* __restrict__ W,
              float* __restrict__ C, int M, int N, int K, int mode, int nh)
{
    __shared__ float As[8][128];
    __shared__ float Bs[8][128];

    const int tid = threadIdx.x;
    const int bm = blockIdx.y, bn = blockIdx.x;
    const float* Ab = A + (size_t)bm * 128 * K;
    const float* Wb = W + (size_t)bn * 128;

    const int arow = tid >> 1;           // 0..127
    const int ac4  = (tid & 1) * 4;      // 0 or 4
    const int brow = tid >> 5;           // 0..7
    const int bcol = (tid & 31) * 4;     // 0..124
    const int tx = tid & 15, ty = tid >> 4;

    float acc[8][8];
#pragma unroll
    for (int i = 0; i < 8; i++)
#pragma unroll
        for (int j = 0; j < 8; j++) acc[i][j] = 0.f;

    for (int k0 = 0; k0 < K; k0 += 8) {
        float4 av = *(const float4*)(Ab + (size_t)arow * K + k0 + ac4);
        float4 bv = *(const float4*)(Wb + (size_t)(k0 + brow) * N + bcol);
        As[ac4 + 0][arow] = av.x;
        As[ac4 + 1][arow] = av.y;
        As[ac4 + 2][arow] = av.z;
        As[ac4 + 3][arow] = av.w;
        *(float4*)&Bs[brow][bcol] = bv;
        __syncthreads();

#pragma unroll
        for (int kk = 0; kk < 8; kk++) {
            float4 a0 = *(float4*)&As[kk][ty * 4];
            float4 a1 = *(float4*)&As[kk][ty * 4 + 64];
            float4 b0 = *(float4*)&Bs[kk][tx * 4];
            float4 b1 = *(float4*)&Bs[kk][tx * 4 + 64];
            float ar[8] = {a0.x, a0.y, a0.z, a0.w, a1.x, a1.y, a1.z, a1.w};
            float br[8] = {b0.x, b0.y, b0.z, b0.w, b1.x, b1.y, b1.z, b1.w};
#pragma unroll
            for (int i = 0; i < 8; i++)
#pragma unroll
                for (int j = 0; j < 8; j++)
                    acc[i][j] = fmaf(ar[i], br[j], acc[i][j]);
        }
        __syncthreads();
    }

#pragma unroll
    for (int ii = 0; ii < 8; ii++) {
        int r = (ii < 4) ? (ty * 4 + ii) : (64 + ty * 4 + ii - 4);
        int m = bm * 128 + r;
#pragma unroll
        for (int jj = 0; jj < 8; jj++) {
            int c = (jj < 4) ? (tx * 4 + jj) : (64 + tx * 4 + jj - 4);
            int n = bn * 128 + c;
            if (mode == 0) {
                C[(size_t)m * N + n] = acc[ii][jj];
            } else {
                int b = m >> 10, s = m & 1023;
                int head = n >> 6, dd = n & 63;
                C[(((size_t)b * nh + head) * SS + s) * HD + dd] = acc[ii][jj];
            }
        }
    }
}

// ---------------------------------------------------------------------------
// RoPE in place on (rows, 64) buffer; row % S = sequence position.
// q'[d]    = q[d]*cos[s,d]    - q[d+32]*sin[s,d]      (d < 32)
// q'[d+32] = q[d+32]*cos[s,d+32] + q[d]*sin[s,d+32]
// ---------------------------------------------------------------------------
__global__ void rope_kernel(float* __restrict__ buf, int nrows,
                            const float* __restrict__ cosb,
                            const float* __restrict__ sinb)
{
    int idx = blockIdx.x * blockDim.x + threadIdx.x;
    if (idx >= nrows * 32) return;
    int row = idx >> 5;
    int d = idx & 31;
    int s = row & (SS - 1);
    float x1 = buf[(size_t)row * HD + d];
    float x2 = buf[(size_t)row * HD + d + 32];
    float c1 = cosb[s * HD + d],      s1 = sinb[s * HD + d];
    float c2 = cosb[s * HD + d + 32], s2 = sinb[s * HD + d + 32];
    buf[(size_t)row * HD + d]      = x1 * c1 - x2 * s1;
    buf[(size_t)row * HD + d + 32] = x2 * c2 + x1 * s2;
}

// ---------------------------------------------------------------------------
// Scores: attn[z, q, k] = (Q[z,q,:] . K[b,kv,k,:]) * 0.125, masked -> -inf
// 64x64 tile per block; grid (ktile, qtile, z=b*NH+h). Tiles above diagonal
// are filled with -inf without compute.
// ---------------------------------------------------------------------------
__global__ __launch_bounds__(256)
void scores_kernel(const float* __restrict__ q, const float* __restrict__ k,
                   const float* __restrict__ mask, float* __restrict__ attn)
{
    const int kt = blockIdx.x, qt = blockIdx.y, z = blockIdx.z;
    const int b = z >> 5, h = z & 31, kvh = h >> 2;
    const int tid = threadIdx.x;
    float* outp = attn + ((size_t)z * SS + qt * 64) * SS + kt * 64;

    if (kt > qt) { // fully masked tile
        float4 ninf = make_float4(-INFINITY, -INFINITY, -INFINITY, -INFINITY);
#pragma unroll
        for (int i = 0; i < 4; i++) {
            int idx = tid + i * 256;
            int r = idx >> 4, c = (idx & 15) * 4;
            *(float4*)(outp + (size_t)r * SS + c) = ninf;
        }
        return;
    }

    const float* Q = q + (size_t)z * SS * HD + qt * 64 * HD;
    const float* Kp = k + ((size_t)(b * NKV + kvh) * SS + kt * 64) * HD;

    __shared__ float Qs[64][64]; // [d][q]
    __shared__ float Ks[64][64]; // [d][k]

#pragma unroll
    for (int i = 0; i < 4; i++) {
        int idx = tid + i * 256;
        int r = idx >> 4, c4 = (idx & 15) * 4;
        float4 qv = *(const float4*)(Q + (size_t)r * HD + c4);
        Qs[c4 + 0][r] = qv.x; Qs[c4 + 1][r] = qv.y;
        Qs[c4 + 2][r] = qv.z; Qs[c4 + 3][r] = qv.w;
        float4 kv = *(const float4*)(Kp + (size_t)r * HD + c4);
        Ks[c4 + 0][r] = kv.x; Ks[c4 + 1][r] = kv.y;
        Ks[c4 + 2][r] = kv.z; Ks[c4 + 3][r] = kv.w;
    }
    __syncthreads();

    const int tx = tid & 15, ty = tid >> 4;
    float acc[4][4];
#pragma unroll
    for (int i = 0; i < 4; i++)
#pragma unroll
        for (int j = 0; j < 4; j++) acc[i][j] = 0.f;

#pragma unroll 8
    for (int d = 0; d < 64; d++) {
        float4 a = *(float4*)&Qs[d][ty * 4];
        float4 bv = *(float4*)&Ks[d][tx * 4];
        float ar[4] = {a.x, a.y, a.z, a.w};
        float br[4] = {bv.x, bv.y, bv.z, bv.w};
#pragma unroll
        for (int i = 0; i < 4; i++)
#pragma unroll
            for (int j = 0; j < 4; j++)
                acc[i][j] = fmaf(ar[i], br[j], acc[i][j]);
    }

#pragma unroll
    for (int i = 0; i < 4; i++) {
        int qg = qt * 64 + ty * 4 + i;
#pragma unroll
        for (int j = 0; j < 4; j++) {
            int kg = kt * 64 + tx * 4 + j;
            float val = acc[i][j] * 0.125f;
            bool ok = (kg <= qg) && (mask[b * SS + kg] == 1.0f);
            outp[(size_t)(ty * 4 + i) * SS + (tx * 4 + j)] = ok ? val : -INFINITY;
        }
    }
}

// ---------------------------------------------------------------------------
// Row softmax in place. One block (256 thr) per row of 1024 floats.
// ---------------------------------------------------------------------------
__global__ __launch_bounds__(256)
void softmax_kernel(float* __restrict__ attn)
{
    const int row = blockIdx.x;
    float* p = attn + (size_t)row * SS;
    const int tid = threadIdx.x;
    const int w = tid >> 5, l = tid & 31;

    float4 v = ((float4*)p)[tid];
    float m = fmaxf(fmaxf(v.x, v.y), fmaxf(v.z, v.w));
#pragma unroll
    for (int off = 16; off > 0; off >>= 1)
        m = fmaxf(m, __shfl_xor_sync(0xffffffffu, m, off));

    __shared__ float red[8];
    __shared__ float bcast[2];
    if (l == 0) red[w] = m;
    __syncthreads();
    if (w == 0) {
        float t = (l < 8) ? red[l] : -INFINITY;
#pragma unroll
        for (int off = 4; off > 0; off >>= 1)
            t = fmaxf(t, __shfl_xor_sync(0xffffffffu, t, off));
        if (l == 0) bcast[0] = t;
    }
    __syncthreads();
    float bmax = bcast[0];

    float4 e;
    e.x = __expf(v.x - bmax);
    e.y = __expf(v.y - bmax);
    e.z = __expf(v.z - bmax);
    e.w = __expf(v.w - bmax);
    float s = e.x + e.y + e.z + e.w;
#pragma unroll
    for (int off = 16; off > 0; off >>= 1)
        s += __shfl_xor_sync(0xffffffffu, s, off);
    __syncthreads();
    if (l == 0) red[w] = s;
    __syncthreads();
    if (w == 0) {
        float t = (l < 8) ? red[l] : 0.f;
#pragma unroll
        for (int off = 4; off > 0; off >>= 1)
            t += __shfl_xor_sync(0xffffffffu, t, off);
        if (l == 0) bcast[1] = t;
    }
    __syncthreads();
    float inv = 1.0f / bcast[1];

    ((float4*)p)[tid] = make_float4(e.x * inv, e.y * inv, e.z * inv, e.w * inv);
}

// ---------------------------------------------------------------------------
// ctx[b, q, h*64+d] = sum_k attn[z,q,k] * v[b,kv,k,d]; causal: k-tiles <= q-tile
// ---------------------------------------------------------------------------
__global__ __launch_bounds__(256)
void ctx_kernel(const float* __restrict__ attn, const float* __restrict__ v,
                float* __restrict__ ctx)
{
    const int qt = blockIdx.y, z = blockIdx.z;
    const int b = z >> 5, h = z & 31, kvh = h >> 2;
    const int tid = threadIdx.x;
    const int tx = tid & 15, ty = tid >> 4;

    const float* P = attn + ((size_t)z * SS + qt * 64) * SS;
    const float* V = v + (size_t)(b * NKV + kvh) * SS * HD;

    __shared__ float Ps[64][64]; // [k][q]
    __shared__ float Vs[64][64]; // [k][d]

    float acc[4][4];
#pragma unroll
    for (int i = 0; i < 4; i++)
#pragma unroll
        for (int j = 0; j < 4; j++) acc[i][j] = 0.f;

    for (int kt = 0; kt <= qt; kt++) {
#pragma unroll
        for (int i = 0; i < 4; i++) {
            int idx = tid + i * 256;
            int r = idx >> 4, c4 = (idx & 15) * 4;
            float4 pv = *(const float4*)(P + (size_t)r * SS + kt * 64 + c4);
            Ps[c4 + 0][r] = pv.x; Ps[c4 + 1][r] = pv.y;
            Ps[c4 + 2][r] = pv.z; Ps[c4 + 3][r] = pv.w;
            *(float4*)&Vs[r][c4] =
                *(const float4*)(V + (size_t)(kt * 64 + r) * HD + c4);
        }
        __syncthreads();

#pragma unroll 8
        for (int kk = 0; kk < 64; kk++) {
            float4 a = *(float4*)&Ps[kk][ty * 4];
            float4 bv = *(float4*)&Vs[kk][tx * 4];
            float ar[4] = {a.x, a.y, a.z, a.w};
            float br[4] = {bv.x, bv.y, bv.z, bv.w};
#pragma unroll
            for (int i = 0; i < 4; i++)
#pragma unroll
                for (int j = 0; j < 4; j++)
                    acc[i][j] = fmaf(ar[i], br[j], acc[i][j]);
        }
        __syncthreads();
    }

#pragma unroll
    for (int i = 0; i < 4; i++) {
        int qg = qt * 64 + ty * 4 + i;
#pragma unroll
        for (int j = 0; j < 4; j++) {
            int dg = tx * 4 + j;
            ctx[((size_t)b * SS + qg) * HID + h * HD + dg] = acc[i][j];
        }
    }
}

// ---------------------------------------------------------------------------
extern "C" void kernel_launch(void* const* d_in, const int* in_sizes, int n_in,
                              void* d_out, int out_size)
{
    const float* hidden = (const float*)d_in[0];
    const float* mask   = (const float*)d_in[1];
    const float* cosb   = (const float*)d_in[2];
    const float* sinb   = (const float*)d_in[3];
    const float* wq     = (const float*)d_in[4];
    const float* wk     = (const float*)d_in[5];
    const float* wv     = (const float*)d_in[6];
    const float* wo     = (const float*)d_in[7];

    float* outp = (float*)d_out;

    float *qp, *kp, *vp, *cp;
    cudaGetSymbolAddress((void**)&qp, g_q);
    cudaGetSymbolAddress((void**)&kp, g_k);
    cudaGetSymbolAddress((void**)&vp, g_v);
    cudaGetSymbolAddress((void**)&cp, g_ctx);

    float* attnp;
    if ((size_t)out_size >= OUT_ELEMS + ATTN_ELEMS) {
        attnp = outp + OUT_ELEMS;           // tuple output: [out, attn] concat
    } else {
        cudaGetSymbolAddress((void**)&attnp, g_attn_fallback);
    }

    // 1) QKV projections (head-split epilogue)
    sgemm128<<<dim3(16, 16), 256>>>(hidden, wq, qp, 2048, 2048, 2048, 1, NH);
    sgemm128<<<dim3(4, 16), 256>>>(hidden, wk, kp, 2048, 512, 2048, 1, NKV);
    sgemm128<<<dim3(4, 16), 256>>>(hidden, wv, vp, 2048, 512, 2048, 1, NKV);

    // 2) RoPE on q and k
    rope_kernel<<<(BB * NH * SS * 32) / 256, 256>>>(qp, BB * NH * SS, cosb, sinb);
    rope_kernel<<<(BB * NKV * SS * 32) / 256, 256>>>(kp, BB * NKV * SS, cosb, sinb);

    // 3) scores -> attn region (masked, scaled)
    scores_kernel<<<dim3(16, 16, BB * NH), 256>>>(qp, kp, mask, attnp);

    // 4) row softmax in place
    softmax_kernel<<<BB * NH * SS, 256>>>(attnp);

    // 5) ctx = attn @ V (causal-limited K loop)
    ctx_kernel<<<dim3(1, 16, BB * NH), 256>>>(attnp, vp, cp);

    // 6) out = ctx @ wo
    sgemm128<<<dim3(16, 16), 256>>>(cp, wo, outp, 2048, 2048, 2048, 0, 0);
}

// round 4
// speedup vs baseline: 2.7081x; 2.7081x over previous
#include <cuda_runtime.h>
#include <math.h>

// Problem constants
#define BB 2
#define SS 1024
#define HID 2048
#define NH 32
#define NKV 8
#define HD 64
#define GROUP 4

#define OUT_ELEMS   (BB * SS * HID)             // 4,194,304
#define ATTN_ELEMS  ((size_t)BB * NH * SS * SS) // 67,108,864

// Scratch (device globals: no runtime allocation allowed)
__device__ float g_q[(size_t)BB * NH * SS * HD];     // (b,h,s,d)
__device__ float g_k[(size_t)BB * NKV * SS * HD];    // (b,kv,s,d)
__device__ float g_v[(size_t)BB * NKV * SS * HD];
__device__ float g_ctx[(size_t)BB * SS * NH * HD];   // (b,s,h*d)
__device__ float g_attn_fallback[ATTN_ELEMS];

// ---------------------------------------------------------------------------
// TF32 helpers
// ---------------------------------------------------------------------------
__device__ __forceinline__ unsigned f2tf(float f) {
    unsigned u;
    asm("cvt.rna.tf32.f32 %0, %1;" : "=r"(u) : "f"(f));
    return u;
}

__device__ __forceinline__ void mma_tf32(float c[4],
                                         unsigned a0, unsigned a1, unsigned a2, unsigned a3,
                                         unsigned b0, unsigned b1)
{
    asm volatile(
        "mma.sync.aligned.m16n8k8.row.col.f32.tf32.tf32.f32 "
        "{%0,%1,%2,%3},{%4,%5,%6,%7},{%8,%9},{%0,%1,%2,%3};"
        : "+f"(c[0]), "+f"(c[1]), "+f"(c[2]), "+f"(c[3])
        : "r"(a0), "r"(a1), "r"(a2), "r"(a3), "r"(b0), "r"(b1));
}

// ---------------------------------------------------------------------------
// TF32 GEMM: C = A[MxK] @ W[KxN], row-major. 128x128 tile, BK=32, 256 thr.
// 8 warps as 2(m) x 4(n); warp tile 64x32 = 4x4 m16n8 tiles.
// As stride 36 (== 4 mod 32), Bs stride 136 (== 8 mod 32): conflict-free LDS.
// mode 0: C[m*N+n];  mode 1: head-split write for (b,h,s,d) layout.
// Requires M%128==0, N%128==0, K%32==0.
// ---------------------------------------------------------------------------
#define AST 36
#define BST 136

__global__ __launch_bounds__(256, 2)
void gemm_tf32(const float* __restrict__ A, const float* __restrict__ W,
               float* __restrict__ C, int M, int N, int K, int mode, int nh)
{
    __shared__ unsigned As[128 * AST];
    __shared__ unsigned Bs[32 * BST];

    const int tid = threadIdx.x;
    const int warp = tid >> 5, lane = tid & 31;
    const int g = lane >> 2, t = lane & 3;
    const int wm = warp >> 2, wn = warp & 3;       // 2 x 4 warp grid
    const int bm = blockIdx.y, bn = blockIdx.x;

    const float* Ab = A + (size_t)bm * 128 * K;
    const float* Wb = W + (size_t)bn * 128;

    float acc[4][4][4];
#pragma unroll
    for (int i = 0; i < 4; i++)
#pragma unroll
        for (int j = 0; j < 4; j++)
#pragma unroll
            for (int r = 0; r < 4; r++) acc[i][j][r] = 0.f;

    for (int k0 = 0; k0 < K; k0 += 32) {
        // A tile: 128 rows x 32 k
#pragma unroll
        for (int l = 0; l < 4; l++) {
            int idx = tid + l * 256;
            int row = idx >> 3, c4 = (idx & 7) * 4;
            float4 v = *(const float4*)(Ab + (size_t)row * K + k0 + c4);
            uint4 u = make_uint4(f2tf(v.x), f2tf(v.y), f2tf(v.z), f2tf(v.w));
            *(uint4*)&As[row * AST + c4] = u;
        }
        // B tile: 32 k rows x 128 n
#pragma unroll
        for (int l = 0; l < 4; l++) {
            int idx = tid + l * 256;
            int kr = idx >> 5, n4 = (idx & 31) * 4;
            float4 v = *(const float4*)(Wb + (size_t)(k0 + kr) * N + n4);
            uint4 u = make_uint4(f2tf(v.x), f2tf(v.y), f2tf(v.z), f2tf(v.w));
            *(uint4*)&Bs[kr * BST + n4] = u;
        }
        __syncthreads();

#pragma unroll
        for (int kb = 0; kb < 32; kb += 8) {
            unsigned a[4][4], b[4][2];
#pragma unroll
            for (int mt = 0; mt < 4; mt++) {
                int rb = wm * 64 + mt * 16;
                a[mt][0] = As[(rb + g) * AST + kb + t];
                a[mt][1] = As[(rb + g + 8) * AST + kb + t];
                a[mt][2] = As[(rb + g) * AST + kb + t + 4];
                a[mt][3] = As[(rb + g + 8) * AST + kb + t + 4];
            }
#pragma unroll
            for (int nt = 0; nt < 4; nt++) {
                int cb = wn * 32 + nt * 8;
                b[nt][0] = Bs[(kb + t) * BST + cb + g];
                b[nt][1] = Bs[(kb + t + 4) * BST + cb + g];
            }
#pragma unroll
            for (int mt = 0; mt < 4; mt++)
#pragma unroll
                for (int nt = 0; nt < 4; nt++)
                    mma_tf32(acc[mt][nt], a[mt][0], a[mt][1], a[mt][2], a[mt][3],
                             b[nt][0], b[nt][1]);
        }
        __syncthreads();
    }

#pragma unroll
    for (int mt = 0; mt < 4; mt++)
#pragma unroll
        for (int nt = 0; nt < 4; nt++)
#pragma unroll
            for (int ri = 0; ri < 4; ri++) {
                int r = wm * 64 + mt * 16 + g + ((ri >= 2) ? 8 : 0);
                int c = wn * 32 + nt * 8 + 2 * t + (ri & 1);
                int m = bm * 128 + r, n = bn * 128 + c;
                if (mode == 0) {
                    C[(size_t)m * N + n] = acc[mt][nt][ri];
                } else {
                    int b_ = m >> 10, s = m & 1023;
                    int head = n >> 6, dd = n & 63;
                    C[(((size_t)b_ * nh + head) * SS + s) * HD + dd] = acc[mt][nt][ri];
                }
            }
}

// ---------------------------------------------------------------------------
// RoPE in place on (rows, 64) buffer; row % S = sequence position.
// ---------------------------------------------------------------------------
__global__ void rope_kernel(float* __restrict__ buf, int nrows,
                            const float* __restrict__ cosb,
                            const float* __restrict__ sinb)
{
    int idx = blockIdx.x * blockDim.x + threadIdx.x;
    if (idx >= nrows * 32) return;
    int row = idx >> 5;
    int d = idx & 31;
    int s = row & (SS - 1);
    float x1 = buf[(size_t)row * HD + d];
    float x2 = buf[(size_t)row * HD + d + 32];
    float c1 = cosb[s * HD + d],      s1 = sinb[s * HD + d];
    float c2 = cosb[s * HD + d + 32], s2 = sinb[s * HD + d + 32];
    buf[(size_t)row * HD + d]      = x1 * c1 - x2 * s1;
    buf[(size_t)row * HD + d + 32] = x2 * c2 + x1 * s2;
}

// ---------------------------------------------------------------------------
// Scores (tf32 mma): attn[z,q,k] = (Q . K) * 0.125, causal+pad masked.
// Block 64x64; 8 warps 2(m) x 4(n); warp tile 32x16 = 2x2 m16n8 tiles.
// Both Q and K tiles stored row-major [pos][d], stride 68 (== 4 mod 32):
// A frags use A-style addressing; B frags read Ks[n][k] (col-major view).
// ---------------------------------------------------------------------------
#define QST 68

__global__ __launch_bounds__(256)
void scores_kernel(const float* __restrict__ q, const float* __restrict__ k,
                   const float* __restrict__ mask, float* __restrict__ attn)
{
    const int kt = blockIdx.x, qt = blockIdx.y, z = blockIdx.z;
    const int b = z >> 5, h = z & 31, kvh = h >> 2;
    const int tid = threadIdx.x;
    float* outp = attn + ((size_t)z * SS + qt * 64) * SS + kt * 64;

    if (kt > qt) { // fully masked tile — no compute
        float4 ninf = make_float4(-INFINITY, -INFINITY, -INFINITY, -INFINITY);
#pragma unroll
        for (int i = 0; i < 4; i++) {
            int idx = tid + i * 256;
            int r = idx >> 4, c = (idx & 15) * 4;
            *(float4*)(outp + (size_t)r * SS + c) = ninf;
        }
        return;
    }

    const float* Q  = q + (size_t)z * SS * HD + qt * 64 * HD;
    const float* Kp = k + ((size_t)(b * NKV + kvh) * SS + kt * 64) * HD;

    __shared__ unsigned Qs[64 * QST];
    __shared__ unsigned Ks[64 * QST];

#pragma unroll
    for (int l = 0; l < 4; l++) {
        int idx = tid + l * 256;
        int row = idx >> 4, c4 = (idx & 15) * 4;
        float4 qv = *(const float4*)(Q + (size_t)row * HD + c4);
        *(uint4*)&Qs[row * QST + c4] =
            make_uint4(f2tf(qv.x), f2tf(qv.y), f2tf(qv.z), f2tf(qv.w));
        float4 kv = *(const float4*)(Kp + (size_t)row * HD + c4);
        *(uint4*)&Ks[row * QST + c4] =
            make_uint4(f2tf(kv.x), f2tf(kv.y), f2tf(kv.z), f2tf(kv.w));
    }
    __syncthreads();

    const int warp = tid >> 5, lane = tid & 31;
    const int g = lane >> 2, t = lane & 3;
    const int wm = warp >> 2, wn = warp & 3;

    float acc[2][2][4];
#pragma unroll
    for (int i = 0; i < 2; i++)
#pragma unroll
        for (int j = 0; j < 2; j++)
#pragma unroll
            for (int r = 0; r < 4; r++) acc[i][j][r] = 0.f;

#pragma unroll
    for (int kb = 0; kb < 64; kb += 8) {
        unsigned a[2][4], bf[2][2];
#pragma unroll
        for (int mt = 0; mt < 2; mt++) {
            int rb = wm * 32 + mt * 16;
            a[mt][0] = Qs[(rb + g) * QST + kb + t];
            a[mt][1] = Qs[(rb + g + 8) * QST + kb + t];
            a[mt][2] = Qs[(rb + g) * QST + kb + t + 4];
            a[mt][3] = Qs[(rb + g + 8) * QST + kb + t + 4];
        }
#pragma unroll
        for (int nt = 0; nt < 2; nt++) {
            int cb = wn * 16 + nt * 8;
            bf[nt][0] = Ks[(cb + g) * QST + kb + t];      // B[k][n] = K[n][k]
            bf[nt][1] = Ks[(cb + g) * QST + kb + t + 4];
        }
#pragma unroll
        for (int mt = 0; mt < 2; mt++)
#pragma unroll
            for (int nt = 0; nt < 2; nt++)
                mma_tf32(acc[mt][nt], a[mt][0], a[mt][1], a[mt][2], a[mt][3],
                         bf[nt][0], bf[nt][1]);
    }

#pragma unroll
    for (int mt = 0; mt < 2; mt++)
#pragma unroll
        for (int nt = 0; nt < 2; nt++)
#pragma unroll
            for (int ri = 0; ri < 4; ri++) {
                int r = wm * 32 + mt * 16 + g + ((ri >= 2) ? 8 : 0);
                int c = wn * 16 + nt * 8 + 2 * t + (ri & 1);
                int qg = qt * 64 + r, kg = kt * 64 + c;
                float val = acc[mt][nt][ri] * 0.125f;
                bool ok = (kg <= qg) && (mask[b * SS + kg] == 1.0f);
                outp[(size_t)r * SS + c] = ok ? val : -INFINITY;
            }
}

// ---------------------------------------------------------------------------
// Row softmax in place. One block (256 thr) per row of 1024 floats.
// ---------------------------------------------------------------------------
__global__ __launch_bounds__(256)
void softmax_kernel(float* __restrict__ attn)
{
    const int row = blockIdx.x;
    float* p = attn + (size_t)row * SS;
    const int tid = threadIdx.x;
    const int w = tid >> 5, l = tid & 31;

    float4 v = ((float4*)p)[tid];
    float m = fmaxf(fmaxf(v.x, v.y), fmaxf(v.z, v.w));
#pragma unroll
    for (int off = 16; off > 0; off >>= 1)
        m = fmaxf(m, __shfl_xor_sync(0xffffffffu, m, off));

    __shared__ float red[8];
    __shared__ float bcast[2];
    if (l == 0) red[w] = m;
    __syncthreads();
    if (w == 0) {
        float t = (l < 8) ? red[l] : -INFINITY;
#pragma unroll
        for (int off = 4; off > 0; off >>= 1)
            t = fmaxf(t, __shfl_xor_sync(0xffffffffu, t, off));
        if (l == 0) bcast[0] = t;
    }
    __syncthreads();
    float bmax = bcast[0];

    float4 e;
    e.x = __expf(v.x - bmax);
    e.y = __expf(v.y - bmax);
    e.z = __expf(v.z - bmax);
    e.w = __expf(v.w - bmax);
    float s = e.x + e.y + e.z + e.w;
#pragma unroll
    for (int off = 16; off > 0; off >>= 1)
        s += __shfl_xor_sync(0xffffffffu, s, off);
    __syncthreads();
    if (l == 0) red[w] = s;
    __syncthreads();
    if (w == 0) {
        float t = (l < 8) ? red[l] : 0.f;
#pragma unroll
        for (int off = 4; off > 0; off >>= 1)
            t += __shfl_xor_sync(0xffffffffu, t, off);
        if (l == 0) bcast[1] = t;
    }
    __syncthreads();
    float inv = 1.0f / bcast[1];

    ((float4*)p)[tid] = make_float4(e.x * inv, e.y * inv, e.z * inv, e.w * inv);
}

// ---------------------------------------------------------------------------
// ctx (tf32 mma): ctx[b,q,h*64+d] = sum_k attn[z,q,k] * v[b,kv,k,d].
// Block 64(q) x 64(d); causal K loop. P stride 68 (A-style), V stride 72
// (B-style, == 8 mod 32); V is naturally k x n row-major.
// ---------------------------------------------------------------------------
#define PST 68
#define VST 72

__global__ __launch_bounds__(256)
void ctx_kernel(const float* __restrict__ attn, const float* __restrict__ v,
                float* __restrict__ ctx)
{
    const int qt = blockIdx.y, z = blockIdx.z;
    const int b = z >> 5, h = z & 31, kvh = h >> 2;
    const int tid = threadIdx.x;
    const int warp = tid >> 5, lane = tid & 31;
    const int g = lane >> 2, t = lane & 3;
    const int wm = warp >> 2, wn = warp & 3;

    const float* P = attn + ((size_t)z * SS + qt * 64) * SS;
    const float* V = v + (size_t)(b * NKV + kvh) * SS * HD;

    __shared__ unsigned Ps[64 * PST];
    __shared__ unsigned Vs[64 * VST];

    float acc[2][2][4];
#pragma unroll
    for (int i = 0; i < 2; i++)
#pragma unroll
        for (int j = 0; j < 2; j++)
#pragma unroll
            for (int r = 0; r < 4; r++) acc[i][j][r] = 0.f;

    for (int kt = 0; kt <= qt; kt++) {
#pragma unroll
        for (int l = 0; l < 4; l++) {
            int idx = tid + l * 256;
            int row = idx >> 4, c4 = (idx & 15) * 4;
            float4 pv = *(const float4*)(P + (size_t)row * SS + kt * 64 + c4);
            *(uint4*)&Ps[row * PST + c4] =
                make_uint4(f2tf(pv.x), f2tf(pv.y), f2tf(pv.z), f2tf(pv.w));
            float4 vv = *(const float4*)(V + (size_t)(kt * 64 + row) * HD + c4);
            *(uint4*)&Vs[row * VST + c4] =
                make_uint4(f2tf(vv.x), f2tf(vv.y), f2tf(vv.z), f2tf(vv.w));
        }
        __syncthreads();

#pragma unroll
        for (int kb = 0; kb < 64; kb += 8) {
            unsigned a[2][4], bf[2][2];
#pragma unroll
            for (int mt = 0; mt < 2; mt++) {
                int rb = wm * 32 + mt * 16;
                a[mt][0] = Ps[(rb + g) * PST + kb + t];
                a[mt][1] = Ps[(rb + g + 8) * PST + kb + t];
                a[mt][2] = Ps[(rb + g) * PST + kb + t + 4];
                a[mt][3] = Ps[(rb + g + 8) * PST + kb + t + 4];
            }
#pragma unroll
            for (int nt = 0; nt < 2; nt++) {
                int cb = wn * 16 + nt * 8;
                bf[nt][0] = Vs[(kb + t) * VST + cb + g];
                bf[nt][1] = Vs[(kb + t + 4) * VST + cb + g];
            }
#pragma unroll
            for (int mt = 0; mt < 2; mt++)
#pragma unroll
                for (int nt = 0; nt < 2; nt++)
                    mma_tf32(acc[mt][nt], a[mt][0], a[mt][1], a[mt][2], a[mt][3],
                             bf[nt][0], bf[nt][1]);
        }
        __syncthreads();
    }

#pragma unroll
    for (int mt = 0; mt < 2; mt++)
#pragma unroll
        for (int nt = 0; nt < 2; nt++)
#pragma unroll
            for (int ri = 0; ri < 4; ri++) {
                int r = wm * 32 + mt * 16 + g + ((ri >= 2) ? 8 : 0);
                int c = wn * 16 + nt * 8 + 2 * t + (ri & 1);
                int qg = qt * 64 + r;
                ctx[((size_t)b * SS + qg) * HID + h * HD + c] = acc[mt][nt][ri];
            }
}

// ---------------------------------------------------------------------------
extern "C" void kernel_launch(void* const* d_in, const int* in_sizes, int n_in,
                              void* d_out, int out_size)
{
    const float* hidden = (const float*)d_in[0];
    const float* mask   = (const float*)d_in[1];
    const float* cosb   = (const float*)d_in[2];
    const float* sinb   = (const float*)d_in[3];
    const float* wq     = (const float*)d_in[4];
    const float* wk     = (const float*)d_in[5];
    const float* wv     = (const float*)d_in[6];
    const float* wo     = (const float*)d_in[7];

    float* outp = (float*)d_out;

    float *qp, *kp, *vp, *cp;
    cudaGetSymbolAddress((void**)&qp, g_q);
    cudaGetSymbolAddress((void**)&kp, g_k);
    cudaGetSymbolAddress((void**)&vp, g_v);
    cudaGetSymbolAddress((void**)&cp, g_ctx);

    float* attnp;
    if ((size_t)out_size >= OUT_ELEMS + ATTN_ELEMS) {
        attnp = outp + OUT_ELEMS;           // tuple output: [out, attn] concat
    } else {
        cudaGetSymbolAddress((void**)&attnp, g_attn_fallback);
    }

    // 1) QKV projections (tf32 tensor cores, head-split epilogue)
    gemm_tf32<<<dim3(16, 16), 256>>>(hidden, wq, qp, 2048, 2048, 2048, 1, NH);
    gemm_tf32<<<dim3(4, 16), 256>>>(hidden, wk, kp, 2048, 512, 2048, 1, NKV);
    gemm_tf32<<<dim3(4, 16), 256>>>(hidden, wv, vp, 2048, 512, 2048, 1, NKV);

    // 2) RoPE on q and k
    rope_kernel<<<(BB * NH * SS * 32) / 256, 256>>>(qp, BB * NH * SS, cosb, sinb);
    rope_kernel<<<(BB * NKV * SS * 32) / 256, 256>>>(kp, BB * NKV * SS, cosb, sinb);

    // 3) scores -> attn region (masked, scaled)
    scores_kernel<<<dim3(16, 16, BB * NH), 256>>>(qp, kp, mask, attnp);

    // 4) row softmax in place
    softmax_kernel<<<BB * NH * SS, 256>>>(attnp);

    // 5) ctx = attn @ V (causal-limited K loop)
    ctx_kernel<<<dim3(1, 16, BB * NH), 256>>>(attnp, vp, cp);

    // 6) out = ctx @ wo
    gemm_tf32<<<dim3(16, 16), 256>>>(cp, wo, outp, 2048, 2048, 2048, 0, 0);
}

// round 5
// speedup vs baseline: 2.8002x; 1.0340x over previous
#include <cuda_runtime.h>
#include <math.h>

// Problem constants
#define BB 2
#define SS 1024
#define HID 2048
#define NH 32
#define NKV 8
#define HD 64
#define GROUP 4

#define OUT_ELEMS   (BB * SS * HID)             // 4,194,304
#define ATTN_ELEMS  ((size_t)BB * NH * SS * SS) // 67,108,864
#define NROWS       (BB * NH * SS)              // 65,536 attn rows
#define NKT         16                          // k-tiles per row

// Scratch (device globals: no runtime allocation allowed)
__device__ float g_q[(size_t)BB * NH * SS * HD];
__device__ float g_k[(size_t)BB * NKV * SS * HD];
__device__ float g_v[(size_t)BB * NKV * SS * HD];
__device__ float g_ctx[(size_t)BB * SS * NH * HD];
__device__ float g_part[(size_t)NROWS * NKT];   // per-row per-ktile exp sums
__device__ float g_inv[NROWS];                  // 1 / row sum
__device__ float g_attn_fallback[ATTN_ELEMS];

// ---------------------------------------------------------------------------
// TF32 helpers
// ---------------------------------------------------------------------------
__device__ __forceinline__ unsigned f2tf(float f) {
    unsigned u;
    asm("cvt.rna.tf32.f32 %0, %1;" : "=r"(u) : "f"(f));
    return u;
}

__device__ __forceinline__ void mma_tf32(float c[4],
                                         unsigned a0, unsigned a1, unsigned a2, unsigned a3,
                                         unsigned b0, unsigned b1)
{
    asm volatile(
        "mma.sync.aligned.m16n8k8.row.col.f32.tf32.tf32.f32 "
        "{%0,%1,%2,%3},{%4,%5,%6,%7},{%8,%9},{%0,%1,%2,%3};"
        : "+f"(c[0]), "+f"(c[1]), "+f"(c[2]), "+f"(c[3])
        : "r"(a0), "r"(a1), "r"(a2), "r"(a3), "r"(b0), "r"(b1));
}

// ---------------------------------------------------------------------------
// TF32 GEMM: C = A[MxK] @ W[KxN], row-major. 128x128 tile, BK=16, 256 thr.
// Register-prefetch double buffering: next tile's LDGs overlap current mma.
// As stride 20 (==4 mod 8 pattern: conflict-free), Bs stride 136 (==8 mod 32).
// mode 0: C[m*N+n];  mode 1: head-split write for (b,h,s,d) layout.
// ---------------------------------------------------------------------------
#define AST 20
#define BST 136

__global__ __launch_bounds__(256, 2)
void gemm_tf32(const float* __restrict__ A, const float* __restrict__ W,
               float* __restrict__ C, int M, int N, int K, int mode, int nh)
{
    __shared__ unsigned As[128 * AST];   // 10.0 KB
    __shared__ unsigned Bs[16 * BST];    //  8.5 KB

    const int tid = threadIdx.x;
    const int warp = tid >> 5, lane = tid & 31;
    const int g = lane >> 2, t = lane & 3;
    const int wm = warp >> 2, wn = warp & 3;       // 2 x 4 warp grid
    const int bm = blockIdx.y, bn = blockIdx.x;

    const float* Ab = A + (size_t)bm * 128 * K;
    const float* Wb = W + (size_t)bn * 128;

    const int arow = tid >> 2;           // 0..63 (plus +64 second load)
    const int ac4  = (tid & 3) * 4;
    const int brow = tid >> 5;           // 0..7 (plus +8)
    const int bn4  = (tid & 31) * 4;

    float acc[4][4][4];
#pragma unroll
    for (int i = 0; i < 4; i++)
#pragma unroll
        for (int j = 0; j < 4; j++)
#pragma unroll
            for (int r = 0; r < 4; r++) acc[i][j][r] = 0.f;

    float4 pa0, pa1, pb0, pb1;
    // prologue: prefetch tile k0=0
    pa0 = *(const float4*)(Ab + (size_t)arow * K + ac4);
    pa1 = *(const float4*)(Ab + (size_t)(arow + 64) * K + ac4);
    pb0 = *(const float4*)(Wb + (size_t)brow * N + bn4);
    pb1 = *(const float4*)(Wb + (size_t)(brow + 8) * N + bn4);

    for (int k0 = 0; k0 < K; k0 += 16) {
        // store prefetched tile to smem (cvt.rna here: once per element)
        As[arow * AST + ac4 + 0] = f2tf(pa0.x);
        As[arow * AST + ac4 + 1] = f2tf(pa0.y);
        As[arow * AST + ac4 + 2] = f2tf(pa0.z);
        As[arow * AST + ac4 + 3] = f2tf(pa0.w);
        As[(arow + 64) * AST + ac4 + 0] = f2tf(pa1.x);
        As[(arow + 64) * AST + ac4 + 1] = f2tf(pa1.y);
        As[(arow + 64) * AST + ac4 + 2] = f2tf(pa1.z);
        As[(arow + 64) * AST + ac4 + 3] = f2tf(pa1.w);
        Bs[brow * BST + bn4 + 0] = f2tf(pb0.x);
        Bs[brow * BST + bn4 + 1] = f2tf(pb0.y);
        Bs[brow * BST + bn4 + 2] = f2tf(pb0.z);
        Bs[brow * BST + bn4 + 3] = f2tf(pb0.w);
        Bs[(brow + 8) * BST + bn4 + 0] = f2tf(pb1.x);
        Bs[(brow + 8) * BST + bn4 + 1] = f2tf(pb1.y);
        Bs[(brow + 8) * BST + bn4 + 2] = f2tf(pb1.z);
        Bs[(brow + 8) * BST + bn4 + 3] = f2tf(pb1.w);
        __syncthreads();

        // prefetch next tile (LDGs overlap the mma loop below)
        if (k0 + 16 < K) {
            pa0 = *(const float4*)(Ab + (size_t)arow * K + k0 + 16 + ac4);
            pa1 = *(const float4*)(Ab + (size_t)(arow + 64) * K + k0 + 16 + ac4);
            pb0 = *(const float4*)(Wb + (size_t)(k0 + 16 + brow) * N + bn4);
            pb1 = *(const float4*)(Wb + (size_t)(k0 + 16 + brow + 8) * N + bn4);
        }

#pragma unroll
        for (int kb = 0; kb < 16; kb += 8) {
            unsigned a[4][4], b[4][2];
#pragma unroll
            for (int mt = 0; mt < 4; mt++) {
                int rb = wm * 64 + mt * 16;
                a[mt][0] = As[(rb + g) * AST + kb + t];
                a[mt][1] = As[(rb + g + 8) * AST + kb + t];
                a[mt][2] = As[(rb + g) * AST + kb + t + 4];
                a[mt][3] = As[(rb + g + 8) * AST + kb + t + 4];
            }
#pragma unroll
            for (int nt = 0; nt < 4; nt++) {
                int cb = wn * 32 + nt * 8;
                b[nt][0] = Bs[(kb + t) * BST + cb + g];
                b[nt][1] = Bs[(kb + t + 4) * BST + cb + g];
            }
#pragma unroll
            for (int mt = 0; mt < 4; mt++)
#pragma unroll
                for (int nt = 0; nt < 4; nt++)
                    mma_tf32(acc[mt][nt], a[mt][0], a[mt][1], a[mt][2], a[mt][3],
                             b[nt][0], b[nt][1]);
        }
        __syncthreads();
    }

#pragma unroll
    for (int mt = 0; mt < 4; mt++)
#pragma unroll
        for (int nt = 0; nt < 4; nt++)
#pragma unroll
            for (int ri = 0; ri < 4; ri++) {
                int r = wm * 64 + mt * 16 + g + ((ri >= 2) ? 8 : 0);
                int c = wn * 32 + nt * 8 + 2 * t + (ri & 1);
                int m = bm * 128 + r, n = bn * 128 + c;
                if (mode == 0) {
                    C[(size_t)m * N + n] = acc[mt][nt][ri];
                } else {
                    int b_ = m >> 10, s = m & 1023;
                    int head = n >> 6, dd = n & 63;
                    C[(((size_t)b_ * nh + head) * SS + s) * HD + dd] = acc[mt][nt][ri];
                }
            }
}

// ---------------------------------------------------------------------------
// RoPE in place on (rows, 64) buffer; row % S = sequence position.
// ---------------------------------------------------------------------------
__global__ void rope_kernel(float* __restrict__ buf, int nrows,
                            const float* __restrict__ cosb,
                            const float* __restrict__ sinb)
{
    int idx = blockIdx.x * blockDim.x + threadIdx.x;
    if (idx >= nrows * 32) return;
    int row = idx >> 5;
    int d = idx & 31;
    int s = row & (SS - 1);
    float x1 = buf[(size_t)row * HD + d];
    float x2 = buf[(size_t)row * HD + d + 32];
    float c1 = cosb[s * HD + d],      s1 = sinb[s * HD + d];
    float c2 = cosb[s * HD + d + 32], s2 = sinb[s * HD + d + 32];
    buf[(size_t)row * HD + d]      = x1 * c1 - x2 * s1;
    buf[(size_t)row * HD + d + 32] = x2 * c2 + x1 * s2;
}

// ---------------------------------------------------------------------------
// Scores: e[z,q,k] = exp((Q.K)/8) (masked -> 0), written UNNORMALIZED.
// Softmax is shift-invariant and |s| is small, so no max subtraction needed.
// Also emits per-(row, ktile) partial sums (deterministic, no atomics).
// ---------------------------------------------------------------------------
#define QST 68

__global__ __launch_bounds__(256)
void scores_kernel(const float* __restrict__ q, const float* __restrict__ k,
                   const float* __restrict__ mask, float* __restrict__ attn,
                   float* __restrict__ part)
{
    const int kt = blockIdx.x, qt = blockIdx.y, z = blockIdx.z;
    const int b = z >> 5, h = z & 31, kvh = h >> 2;
    const int tid = threadIdx.x;
    float* outp = attn + ((size_t)z * SS + qt * 64) * SS + kt * 64;

    if (kt > qt) { // fully masked tile: attn (post-softmax) is 0 here
        float4 zero = make_float4(0.f, 0.f, 0.f, 0.f);
#pragma unroll
        for (int i = 0; i < 4; i++) {
            int idx = tid + i * 256;
            int r = idx >> 4, c = (idx & 15) * 4;
            *(float4*)(outp + (size_t)r * SS + c) = zero;
        }
        return;
    }

    const float* Q  = q + (size_t)z * SS * HD + qt * 64 * HD;
    const float* Kp = k + ((size_t)(b * NKV + kvh) * SS + kt * 64) * HD;

    __shared__ unsigned Qs[64 * QST];
    __shared__ unsigned Ks[64 * QST];
    __shared__ float rp[64][4];

#pragma unroll
    for (int l = 0; l < 4; l++) {
        int idx = tid + l * 256;
        int row = idx >> 4, c4 = (idx & 15) * 4;
        float4 qv = *(const float4*)(Q + (size_t)row * HD + c4);
        *(uint4*)&Qs[row * QST + c4] =
            make_uint4(f2tf(qv.x), f2tf(qv.y), f2tf(qv.z), f2tf(qv.w));
        float4 kv = *(const float4*)(Kp + (size_t)row * HD + c4);
        *(uint4*)&Ks[row * QST + c4] =
            make_uint4(f2tf(kv.x), f2tf(kv.y), f2tf(kv.z), f2tf(kv.w));
    }
    __syncthreads();

    const int warp = tid >> 5, lane = tid & 31;
    const int g = lane >> 2, t = lane & 3;
    const int wm = warp >> 2, wn = warp & 3;

    float acc[2][2][4];
#pragma unroll
    for (int i = 0; i < 2; i++)
#pragma unroll
        for (int j = 0; j < 2; j++)
#pragma unroll
            for (int r = 0; r < 4; r++) acc[i][j][r] = 0.f;

#pragma unroll
    for (int kb = 0; kb < 64; kb += 8) {
        unsigned a[2][4], bf[2][2];
#pragma unroll
        for (int mt = 0; mt < 2; mt++) {
            int rb = wm * 32 + mt * 16;
            a[mt][0] = Qs[(rb + g) * QST + kb + t];
            a[mt][1] = Qs[(rb + g + 8) * QST + kb + t];
            a[mt][2] = Qs[(rb + g) * QST + kb + t + 4];
            a[mt][3] = Qs[(rb + g + 8) * QST + kb + t + 4];
        }
#pragma unroll
        for (int nt = 0; nt < 2; nt++) {
            int cb = wn * 16 + nt * 8;
            bf[nt][0] = Ks[(cb + g) * QST + kb + t];
            bf[nt][1] = Ks[(cb + g) * QST + kb + t + 4];
        }
#pragma unroll
        for (int mt = 0; mt < 2; mt++)
#pragma unroll
            for (int nt = 0; nt < 2; nt++)
                mma_tf32(acc[mt][nt], a[mt][0], a[mt][1], a[mt][2], a[mt][3],
                         bf[nt][0], bf[nt][1]);
    }

    float rs[2][2] = {{0.f, 0.f}, {0.f, 0.f}};
#pragma unroll
    for (int mt = 0; mt < 2; mt++)
#pragma unroll
        for (int nt = 0; nt < 2; nt++)
#pragma unroll
            for (int ri = 0; ri < 4; ri++) {
                int r = wm * 32 + mt * 16 + g + ((ri >= 2) ? 8 : 0);
                int c = wn * 16 + nt * 8 + 2 * t + (ri & 1);
                int qg = qt * 64 + r, kg = kt * 64 + c;
                bool ok = (kg <= qg) && (mask[b * SS + kg] == 1.0f);
                float e = ok ? __expf(acc[mt][nt][ri] * 0.125f) : 0.f;
                outp[(size_t)r * SS + c] = e;
                rs[mt][ri >> 1] += e;
            }

    // reduce over t-lanes (same rows), write per-warp 16-col partials
#pragma unroll
    for (int mt = 0; mt < 2; mt++)
#pragma unroll
        for (int hi = 0; hi < 2; hi++) {
            float v = rs[mt][hi];
            v += __shfl_xor_sync(0xffffffffu, v, 1);
            v += __shfl_xor_sync(0xffffffffu, v, 2);
            if (t == 0)
                rp[wm * 32 + mt * 16 + hi * 8 + g][wn] = v;
        }
    __syncthreads();

    if (tid < 64) {
        float s = rp[tid][0] + rp[tid][1] + rp[tid][2] + rp[tid][3];
        part[((size_t)z * SS + qt * 64 + tid) * NKT + kt] = s;
    }
}

// ---------------------------------------------------------------------------
// Combine partial sums -> 1/rowsum. One thread per attn row.
// ---------------------------------------------------------------------------
__global__ void combine_kernel(const float* __restrict__ part,
                               float* __restrict__ inv)
{
    int row = blockIdx.x * blockDim.x + threadIdx.x;
    if (row >= NROWS) return;
    int qt = (row & (SS - 1)) >> 6;
    float s = 0.f;
    for (int kt = 0; kt <= qt; kt++) s += part[(size_t)row * NKT + kt];
    inv[row] = 1.0f / s;
}

// ---------------------------------------------------------------------------
// ctx: normalizes attn in place (writes final softmax output) and computes
// ctx[b,q,h*64+d] = sum_k p[z,q,k] * v[b,kv,k,d], causal K loop.
// ---------------------------------------------------------------------------
#define PST 68
#define VST 72

__global__ __launch_bounds__(256)
void ctx_kernel(float* __restrict__ attn, const float* __restrict__ v,
                const float* __restrict__ inv, float* __restrict__ ctx)
{
    const int qt = blockIdx.y, z = blockIdx.z;
    const int b = z >> 5, h = z & 31, kvh = h >> 2;
    const int tid = threadIdx.x;
    const int warp = tid >> 5, lane = tid & 31;
    const int g = lane >> 2, t = lane & 3;
    const int wm = warp >> 2, wn = warp & 3;

    float* P = attn + ((size_t)z * SS + qt * 64) * SS;
    const float* V = v + (size_t)(b * NKV + kvh) * SS * HD;
    const float* invr = inv + (size_t)z * SS + qt * 64;

    __shared__ unsigned Ps[64 * PST];
    __shared__ unsigned Vs[64 * VST];

    float acc[2][2][4];
#pragma unroll
    for (int i = 0; i < 2; i++)
#pragma unroll
        for (int j = 0; j < 2; j++)
#pragma unroll
            for (int r = 0; r < 4; r++) acc[i][j][r] = 0.f;

    for (int kt = 0; kt <= qt; kt++) {
#pragma unroll
        for (int l = 0; l < 4; l++) {
            int idx = tid + l * 256;
            int row = idx >> 4, c4 = (idx & 15) * 4;
            float iv = invr[row];
            float4 pv = *(const float4*)(P + (size_t)row * SS + kt * 64 + c4);
            pv.x *= iv; pv.y *= iv; pv.z *= iv; pv.w *= iv;
            // write final normalized attention (required output)
            *(float4*)(P + (size_t)row * SS + kt * 64 + c4) = pv;
            *(uint4*)&Ps[row * PST + c4] =
                make_uint4(f2tf(pv.x), f2tf(pv.y), f2tf(pv.z), f2tf(pv.w));
            float4 vv = *(const float4*)(V + (size_t)(kt * 64 + row) * HD + c4);
            *(uint4*)&Vs[row * VST + c4] =
                make_uint4(f2tf(vv.x), f2tf(vv.y), f2tf(vv.z), f2tf(vv.w));
        }
        __syncthreads();

#pragma unroll
        for (int kb = 0; kb < 64; kb += 8) {
            unsigned a[2][4], bf[2][2];
#pragma unroll
            for (int mt = 0; mt < 2; mt++) {
                int rb = wm * 32 + mt * 16;
                a[mt][0] = Ps[(rb + g) * PST + kb + t];
                a[mt][1] = Ps[(rb + g + 8) * PST + kb + t];
                a[mt][2] = Ps[(rb + g) * PST + kb + t + 4];
                a[mt][3] = Ps[(rb + g + 8) * PST + kb + t + 4];
            }
#pragma unroll
            for (int nt = 0; nt < 2; nt++) {
                int cb = wn * 16 + nt * 8;
                bf[nt][0] = Vs[(kb + t) * VST + cb + g];
                bf[nt][1] = Vs[(kb + t + 4) * VST + cb + g];
            }
#pragma unroll
            for (int mt = 0; mt < 2; mt++)
#pragma unroll
                for (int nt = 0; nt < 2; nt++)
                    mma_tf32(acc[mt][nt], a[mt][0], a[mt][1], a[mt][2], a[mt][3],
                             bf[nt][0], bf[nt][1]);
        }
        __syncthreads();
    }

#pragma unroll
    for (int mt = 0; mt < 2; mt++)
#pragma unroll
        for (int nt = 0; nt < 2; nt++)
#pragma unroll
            for (int ri = 0; ri < 4; ri++) {
                int r = wm * 32 + mt * 16 + g + ((ri >= 2) ? 8 : 0);
                int c = wn * 16 + nt * 8 + 2 * t + (ri & 1);
                int qg = qt * 64 + r;
                ctx[((size_t)b * SS + qg) * HID + h * HD + c] = acc[mt][nt][ri];
            }
}

// ---------------------------------------------------------------------------
extern "C" void kernel_launch(void* const* d_in, const int* in_sizes, int n_in,
                              void* d_out, int out_size)
{
    const float* hidden = (const float*)d_in[0];
    const float* mask   = (const float*)d_in[1];
    const float* cosb   = (const float*)d_in[2];
    const float* sinb   = (const float*)d_in[3];
    const float* wq     = (const float*)d_in[4];
    const float* wk     = (const float*)d_in[5];
    const float* wv     = (const float*)d_in[6];
    const float* wo     = (const float*)d_in[7];

    float* outp = (float*)d_out;

    float *qp, *kp, *vp, *cp, *pp, *ip;
    cudaGetSymbolAddress((void**)&qp, g_q);
    cudaGetSymbolAddress((void**)&kp, g_k);
    cudaGetSymbolAddress((void**)&vp, g_v);
    cudaGetSymbolAddress((void**)&cp, g_ctx);
    cudaGetSymbolAddress((void**)&pp, g_part);
    cudaGetSymbolAddress((void**)&ip, g_inv);

    float* attnp;
    if ((size_t)out_size >= OUT_ELEMS + ATTN_ELEMS) {
        attnp = outp + OUT_ELEMS;           // tuple output: [out, attn] concat
    } else {
        cudaGetSymbolAddress((void**)&attnp, g_attn_fallback);
    }

    // 1) QKV projections (pipelined tf32 tensor cores)
    gemm_tf32<<<dim3(16, 16), 256>>>(hidden, wq, qp, 2048, 2048, 2048, 1, NH);
    gemm_tf32<<<dim3(4, 16), 256>>>(hidden, wk, kp, 2048, 512, 2048, 1, NKV);
    gemm_tf32<<<dim3(4, 16), 256>>>(hidden, wv, vp, 2048, 512, 2048, 1, NKV);

    // 2) RoPE on q and k
    rope_kernel<<<(BB * NH * SS * 32) / 256, 256>>>(qp, BB * NH * SS, cosb, sinb);
    rope_kernel<<<(BB * NKV * SS * 32) / 256, 256>>>(kp, BB * NKV * SS, cosb, sinb);

    // 3) scores -> unnormalized exp + partial row sums (softmax fused away)
    scores_kernel<<<dim3(16, 16, BB * NH), 256>>>(qp, kp, mask, attnp, pp);

    // 4) combine partials -> 1/rowsum
    combine_kernel<<<NROWS / 256, 256>>>(pp, ip);

    // 5) ctx = attn @ V; normalizes attn in place (final output)
    ctx_kernel<<<dim3(1, 16, BB * NH), 256>>>(attnp, vp, ip, cp);

    // 6) out = ctx @ wo
    gemm_tf32<<<dim3(16, 16), 256>>>(cp, wo, outp, 2048, 2048, 2048, 0, 0);
}

// round 6
// speedup vs baseline: 3.6628x; 1.3080x over previous
#include <cuda_runtime.h>
#include <math.h>

// Problem constants
#define BB 2
#define SS 1024
#define HID 2048
#define NH 32
#define NKV 8
#define HD 64
#define GROUP 4

#define OUT_ELEMS   (BB * SS * HID)             // 4,194,304
#define ATTN_ELEMS  ((size_t)BB * NH * SS * SS) // 67,108,864
#define NROWS       (BB * NH * SS)              // 65,536 attn rows
#define NKT         16                          // k-tiles per row

// Scratch (device globals: no runtime allocation allowed)
__device__ float g_q[(size_t)BB * NH * SS * HD];
__device__ float g_k[(size_t)BB * NKV * SS * HD];
__device__ float g_v[(size_t)BB * NKV * SS * HD];
__device__ float g_ctx[(size_t)BB * SS * NH * HD];
__device__ float g_part[(size_t)NROWS * NKT];
__device__ float g_inv[NROWS];
__device__ float g_attn_fallback[ATTN_ELEMS];

// ---------------------------------------------------------------------------
// TF32 helpers
// ---------------------------------------------------------------------------
__device__ __forceinline__ unsigned f2tf(float f) {
    unsigned u;
    asm("cvt.rna.tf32.f32 %0, %1;" : "=r"(u) : "f"(f));
    return u;
}

__device__ __forceinline__ void mma_tf32(float c[4],
                                         unsigned a0, unsigned a1, unsigned a2, unsigned a3,
                                         unsigned b0, unsigned b1)
{
    asm volatile(
        "mma.sync.aligned.m16n8k8.row.col.f32.tf32.tf32.f32 "
        "{%0,%1,%2,%3},{%4,%5,%6,%7},{%8,%9},{%0,%1,%2,%3};"
        : "+f"(c[0]), "+f"(c[1]), "+f"(c[2]), "+f"(c[3])
        : "r"(a0), "r"(a1), "r"(a2), "r"(a3), "r"(b0), "r"(b1));
}

__device__ __forceinline__ void cpa16(void* s, const void* g) {
    unsigned sa = (unsigned)__cvta_generic_to_shared(s);
    asm volatile("cp.async.cg.shared.global [%0], [%1], 16;" :: "r"(sa), "l"(g));
}

// ---------------------------------------------------------------------------
// GEMM mainloop: 128x128 tile, BK=16, 2-stage cp.async double buffering.
// A tile smem stride AST=20, B tile stride BST=136 (conflict-free patterns).
// fp32 kept in smem; cvt.rna at fragment-load time (ALU pipe).
// ---------------------------------------------------------------------------
#define AST 20
#define BST 136

__device__ __forceinline__ void gemm_mainloop(
    const float* __restrict__ Ab, const float* __restrict__ Wb,
    int N, int K, float acc[4][4][4], float* As, float* Bs)
{
    const int tid = threadIdx.x;
    const int warp = tid >> 5, lane = tid & 31;
    const int g = lane >> 2, t = lane & 3;
    const int wm = warp >> 2, wn = warp & 3;
    const int arow = tid >> 2, ac4 = (tid & 3) * 4;
    const int brow = tid >> 5, bn4 = (tid & 31) * 4;

    const int ntiles = K / 16;

    // prologue: stage 0
    {
        cpa16(&As[arow * AST + ac4],        Ab + (size_t)arow * K + ac4);
        cpa16(&As[(arow + 64) * AST + ac4], Ab + (size_t)(arow + 64) * K + ac4);
        cpa16(&Bs[brow * BST + bn4],        Wb + (size_t)brow * N + bn4);
        cpa16(&Bs[(brow + 8) * BST + bn4],  Wb + (size_t)(brow + 8) * N + bn4);
        asm volatile("cp.async.commit_group;");
    }

    for (int i = 0; i < ntiles; i++) {
        if (i + 1 < ntiles) {
            const int k0 = (i + 1) * 16;
            float* An = As + ((i + 1) & 1) * 128 * AST;
            float* Bn = Bs + ((i + 1) & 1) * 16 * BST;
            cpa16(&An[arow * AST + ac4],        Ab + (size_t)arow * K + k0 + ac4);
            cpa16(&An[(arow + 64) * AST + ac4], Ab + (size_t)(arow + 64) * K + k0 + ac4);
            cpa16(&Bn[brow * BST + bn4],        Wb + (size_t)(k0 + brow) * N + bn4);
            cpa16(&Bn[(brow + 8) * BST + bn4],  Wb + (size_t)(k0 + brow + 8) * N + bn4);
            asm volatile("cp.async.commit_group;");
            asm volatile("cp.async.wait_group 1;");
        } else {
            asm volatile("cp.async.wait_group 0;");
        }
        __syncthreads();

        const float* Ac = As + (i & 1) * 128 * AST;
        const float* Bc = Bs + (i & 1) * 16 * BST;

#pragma unroll
        for (int kb = 0; kb < 16; kb += 8) {
            unsigned a[4][4], b[4][2];
#pragma unroll
            for (int mt = 0; mt < 4; mt++) {
                int rb = wm * 64 + mt * 16;
                a[mt][0] = f2tf(Ac[(rb + g) * AST + kb + t]);
                a[mt][1] = f2tf(Ac[(rb + g + 8) * AST + kb + t]);
                a[mt][2] = f2tf(Ac[(rb + g) * AST + kb + t + 4]);
                a[mt][3] = f2tf(Ac[(rb + g + 8) * AST + kb + t + 4]);
            }
#pragma unroll
            for (int nt = 0; nt < 4; nt++) {
                int cb = wn * 32 + nt * 8;
                b[nt][0] = f2tf(Bc[(kb + t) * BST + cb + g]);
                b[nt][1] = f2tf(Bc[(kb + t + 4) * BST + cb + g]);
            }
#pragma unroll
            for (int mt = 0; mt < 4; mt++)
#pragma unroll
                for (int nt = 0; nt < 4; nt++)
                    mma_tf32(acc[mt][nt], a[mt][0], a[mt][1], a[mt][2], a[mt][3],
                             b[nt][0], b[nt][1]);
        }
        __syncthreads();
    }
}

// ---------------------------------------------------------------------------
// Fused QKV projection: grid (24, 16). bn<16 -> Q, bn<20 -> K, else V.
// Head-split epilogue into (b,h,s,d).
// ---------------------------------------------------------------------------
__global__ __launch_bounds__(256, 2)
void qkv_kernel(const float* __restrict__ hidden,
                const float* __restrict__ wq, const float* __restrict__ wk,
                const float* __restrict__ wv,
                float* __restrict__ qo, float* __restrict__ ko,
                float* __restrict__ vo)
{
    __shared__ float As[2 * 128 * AST];
    __shared__ float Bs[2 * 16 * BST];

    const int bn = blockIdx.x, bm = blockIdx.y;
    const float* W; float* C; int N, nh, bl;
    if (bn < 16)      { W = wq; C = qo; N = 2048; nh = NH;  bl = bn; }
    else if (bn < 20) { W = wk; C = ko; N = 512;  nh = NKV; bl = bn - 16; }
    else              { W = wv; C = vo; N = 512;  nh = NKV; bl = bn - 20; }

    const float* Ab = hidden + (size_t)bm * 128 * 2048;
    const float* Wb = W + bl * 128;

    float acc[4][4][4];
#pragma unroll
    for (int i = 0; i < 4; i++)
#pragma unroll
        for (int j = 0; j < 4; j++)
#pragma unroll
            for (int r = 0; r < 4; r++) acc[i][j][r] = 0.f;

    gemm_mainloop(Ab, Wb, N, 2048, acc, As, Bs);

    const int tid = threadIdx.x;
    const int warp = tid >> 5, lane = tid & 31;
    const int g = lane >> 2, t = lane & 3;
    const int wm = warp >> 2, wn = warp & 3;

#pragma unroll
    for (int mt = 0; mt < 4; mt++)
#pragma unroll
        for (int nt = 0; nt < 4; nt++)
#pragma unroll
            for (int ri = 0; ri < 4; ri++) {
                int r = wm * 64 + mt * 16 + g + ((ri >= 2) ? 8 : 0);
                int c = wn * 32 + nt * 8 + 2 * t + (ri & 1);
                int m = bm * 128 + r, n = bl * 128 + c;
                int b_ = m >> 10, s = m & 1023;
                int head = n >> 6, dd = n & 63;
                C[(((size_t)b_ * nh + head) * SS + s) * HD + dd] = acc[mt][nt][ri];
            }
}

// ---------------------------------------------------------------------------
// Plain GEMM (out projection): C[m*N+n] = A @ W.
// ---------------------------------------------------------------------------
__global__ __launch_bounds__(256, 2)
void gemm_kernel(const float* __restrict__ A, const float* __restrict__ W,
                 float* __restrict__ C, int M, int N, int K)
{
    __shared__ float As[2 * 128 * AST];
    __shared__ float Bs[2 * 16 * BST];

    const int bn = blockIdx.x, bm = blockIdx.y;
    const float* Ab = A + (size_t)bm * 128 * K;
    const float* Wb = W + bn * 128;

    float acc[4][4][4];
#pragma unroll
    for (int i = 0; i < 4; i++)
#pragma unroll
        for (int j = 0; j < 4; j++)
#pragma unroll
            for (int r = 0; r < 4; r++) acc[i][j][r] = 0.f;

    gemm_mainloop(Ab, Wb, N, K, acc, As, Bs);

    const int tid = threadIdx.x;
    const int warp = tid >> 5, lane = tid & 31;
    const int g = lane >> 2, t = lane & 3;
    const int wm = warp >> 2, wn = warp & 3;

#pragma unroll
    for (int mt = 0; mt < 4; mt++)
#pragma unroll
        for (int nt = 0; nt < 4; nt++)
#pragma unroll
            for (int ri = 0; ri < 4; ri++) {
                int r = wm * 64 + mt * 16 + g + ((ri >= 2) ? 8 : 0);
                int c = wn * 32 + nt * 8 + 2 * t + (ri & 1);
                int m = bm * 128 + r, n = bn * 128 + c;
                C[(size_t)m * N + n] = acc[mt][nt][ri];
            }
}

// ---------------------------------------------------------------------------
// RoPE in place on (rows, 64) buffer; row % S = sequence position.
// ---------------------------------------------------------------------------
__global__ void rope_kernel(float* __restrict__ buf, int nrows,
                            const float* __restrict__ cosb,
                            const float* __restrict__ sinb)
{
    int idx = blockIdx.x * blockDim.x + threadIdx.x;
    if (idx >= nrows * 32) return;
    int row = idx >> 5;
    int d = idx & 31;
    int s = row & (SS - 1);
    float x1 = buf[(size_t)row * HD + d];
    float x2 = buf[(size_t)row * HD + d + 32];
    float c1 = cosb[s * HD + d],      s1 = sinb[s * HD + d];
    float c2 = cosb[s * HD + d + 32], s2 = sinb[s * HD + d + 32];
    buf[(size_t)row * HD + d]      = x1 * c1 - x2 * s1;
    buf[(size_t)row * HD + d + 32] = x2 * c2 + x1 * s2;
}

// ---------------------------------------------------------------------------
// Scores: e[z,q,k] = exp((Q.K)/8) (masked -> 0), written UNNORMALIZED,
// plus per-(row, ktile) partial sums. Softmax shift-invariance: no max needed.
// ---------------------------------------------------------------------------
#define QST 68

__global__ __launch_bounds__(256)
void scores_kernel(const float* __restrict__ q, const float* __restrict__ k,
                   const float* __restrict__ mask, float* __restrict__ attn,
                   float* __restrict__ part)
{
    const int kt = blockIdx.x, qt = blockIdx.y, z = blockIdx.z;
    const int b = z >> 5, h = z & 31, kvh = h >> 2;
    const int tid = threadIdx.x;
    float* outp = attn + ((size_t)z * SS + qt * 64) * SS + kt * 64;

    if (kt > qt) { // fully masked tile: post-softmax attn is 0 here
        float4 zero = make_float4(0.f, 0.f, 0.f, 0.f);
#pragma unroll
        for (int i = 0; i < 4; i++) {
            int idx = tid + i * 256;
            int r = idx >> 4, c = (idx & 15) * 4;
            *(float4*)(outp + (size_t)r * SS + c) = zero;
        }
        return;
    }

    const float* Q  = q + (size_t)z * SS * HD + qt * 64 * HD;
    const float* Kp = k + ((size_t)(b * NKV + kvh) * SS + kt * 64) * HD;

    __shared__ unsigned Qs[64 * QST];
    __shared__ unsigned Ks[64 * QST];
    __shared__ float rp[64][4];

#pragma unroll
    for (int l = 0; l < 4; l++) {
        int idx = tid + l * 256;
        int row = idx >> 4, c4 = (idx & 15) * 4;
        float4 qv = *(const float4*)(Q + (size_t)row * HD + c4);
        *(uint4*)&Qs[row * QST + c4] =
            make_uint4(f2tf(qv.x), f2tf(qv.y), f2tf(qv.z), f2tf(qv.w));
        float4 kv = *(const float4*)(Kp + (size_t)row * HD + c4);
        *(uint4*)&Ks[row * QST + c4] =
            make_uint4(f2tf(kv.x), f2tf(kv.y), f2tf(kv.z), f2tf(kv.w));
    }
    __syncthreads();

    const int warp = tid >> 5, lane = tid & 31;
    const int g = lane >> 2, t = lane & 3;
    const int wm = warp >> 2, wn = warp & 3;

    float acc[2][2][4];
#pragma unroll
    for (int i = 0; i < 2; i++)
#pragma unroll
        for (int j = 0; j < 2; j++)
#pragma unroll
            for (int r = 0; r < 4; r++) acc[i][j][r] = 0.f;

#pragma unroll
    for (int kb = 0; kb < 64; kb += 8) {
        unsigned a[2][4], bf[2][2];
#pragma unroll
        for (int mt = 0; mt < 2; mt++) {
            int rb = wm * 32 + mt * 16;
            a[mt][0] = Qs[(rb + g) * QST + kb + t];
            a[mt][1] = Qs[(rb + g + 8) * QST + kb + t];
            a[mt][2] = Qs[(rb + g) * QST + kb + t + 4];
            a[mt][3] = Qs[(rb + g + 8) * QST + kb + t + 4];
        }
#pragma unroll
        for (int nt = 0; nt < 2; nt++) {
            int cb = wn * 16 + nt * 8;
            bf[nt][0] = Ks[(cb + g) * QST + kb + t];
            bf[nt][1] = Ks[(cb + g) * QST + kb + t + 4];
        }
#pragma unroll
        for (int mt = 0; mt < 2; mt++)
#pragma unroll
            for (int nt = 0; nt < 2; nt++)
                mma_tf32(acc[mt][nt], a[mt][0], a[mt][1], a[mt][2], a[mt][3],
                         bf[nt][0], bf[nt][1]);
    }

    float rs[2][2] = {{0.f, 0.f}, {0.f, 0.f}};
#pragma unroll
    for (int mt = 0; mt < 2; mt++)
#pragma unroll
        for (int nt = 0; nt < 2; nt++)
#pragma unroll
            for (int ri = 0; ri < 4; ri++) {
                int r = wm * 32 + mt * 16 + g + ((ri >= 2) ? 8 : 0);
                int c = wn * 16 + nt * 8 + 2 * t + (ri & 1);
                int qg = qt * 64 + r, kg = kt * 64 + c;
                bool ok = (kg <= qg) && (mask[b * SS + kg] == 1.0f);
                float e = ok ? __expf(acc[mt][nt][ri] * 0.125f) : 0.f;
                outp[(size_t)r * SS + c] = e;
                rs[mt][ri >> 1] += e;
            }

#pragma unroll
    for (int mt = 0; mt < 2; mt++)
#pragma unroll
        for (int hi = 0; hi < 2; hi++) {
            float v = rs[mt][hi];
            v += __shfl_xor_sync(0xffffffffu, v, 1);
            v += __shfl_xor_sync(0xffffffffu, v, 2);
            if (t == 0)
                rp[wm * 32 + mt * 16 + hi * 8 + g][wn] = v;
        }
    __syncthreads();

    if (tid < 64) {
        float s = rp[tid][0] + rp[tid][1] + rp[tid][2] + rp[tid][3];
        part[((size_t)z * SS + qt * 64 + tid) * NKT + kt] = s;
    }
}

// ---------------------------------------------------------------------------
// Combine partial sums -> 1/rowsum.
// ---------------------------------------------------------------------------
__global__ void combine_kernel(const float* __restrict__ part,
                               float* __restrict__ inv)
{
    int row = blockIdx.x * blockDim.x + threadIdx.x;
    if (row >= NROWS) return;
    int qt = (row & (SS - 1)) >> 6;
    float s = 0.f;
    for (int kt = 0; kt <= qt; kt++) s += part[(size_t)row * NKT + kt];
    inv[row] = 1.0f / s;
}

// ---------------------------------------------------------------------------
// ctx: normalizes attn in place (final attn output) and ctx = P @ V.
// qt reversed (heaviest blocks first) for load balance.
// ---------------------------------------------------------------------------
#define PST 68
#define VST 72

__global__ __launch_bounds__(256)
void ctx_kernel(float* __restrict__ attn, const float* __restrict__ v,
                const float* __restrict__ inv, float* __restrict__ ctx)
{
    const int qt = 15 - blockIdx.y, z = blockIdx.z;
    const int b = z >> 5, h = z & 31, kvh = h >> 2;
    const int tid = threadIdx.x;
    const int warp = tid >> 5, lane = tid & 31;
    const int g = lane >> 2, t = lane & 3;
    const int wm = warp >> 2, wn = warp & 3;

    float* P = attn + ((size_t)z * SS + qt * 64) * SS;
    const float* V = v + (size_t)(b * NKV + kvh) * SS * HD;
    const float* invr = inv + (size_t)z * SS + qt * 64;

    __shared__ unsigned Ps[64 * PST];
    __shared__ unsigned Vs[64 * VST];

    float acc[2][2][4];
#pragma unroll
    for (int i = 0; i < 2; i++)
#pragma unroll
        for (int j = 0; j < 2; j++)
#pragma unroll
            for (int r = 0; r < 4; r++) acc[i][j][r] = 0.f;

    for (int kt = 0; kt <= qt; kt++) {
#pragma unroll
        for (int l = 0; l < 4; l++) {
            int idx = tid + l * 256;
            int row = idx >> 4, c4 = (idx & 15) * 4;
            float iv = invr[row];
            float4 pv = *(const float4*)(P + (size_t)row * SS + kt * 64 + c4);
            pv.x *= iv; pv.y *= iv; pv.z *= iv; pv.w *= iv;
            *(float4*)(P + (size_t)row * SS + kt * 64 + c4) = pv;
            *(uint4*)&Ps[row * PST + c4] =
                make_uint4(f2tf(pv.x), f2tf(pv.y), f2tf(pv.z), f2tf(pv.w));
            float4 vv = *(const float4*)(V + (size_t)(kt * 64 + row) * HD + c4);
            *(uint4*)&Vs[row * VST + c4] =
                make_uint4(f2tf(vv.x), f2tf(vv.y), f2tf(vv.z), f2tf(vv.w));
        }
        __syncthreads();

#pragma unroll
        for (int kb = 0; kb < 64; kb += 8) {
            unsigned a[2][4], bf[2][2];
#pragma unroll
            for (int mt = 0; mt < 2; mt++) {
                int rb = wm * 32 + mt * 16;
                a[mt][0] = Ps[(rb + g) * PST + kb + t];
                a[mt][1] = Ps[(rb + g + 8) * PST + kb + t];
                a[mt][2] = Ps[(rb + g) * PST + kb + t + 4];
                a[mt][3] = Ps[(rb + g + 8) * PST + kb + t + 4];
            }
#pragma unroll
            for (int nt = 0; nt < 2; nt++) {
                int cb = wn * 16 + nt * 8;
                bf[nt][0] = Vs[(kb + t) * VST + cb + g];
                bf[nt][1] = Vs[(kb + t + 4) * VST + cb + g];
            }
#pragma unroll
            for (int mt = 0; mt < 2; mt++)
#pragma unroll
                for (int nt = 0; nt < 2; nt++)
                    mma_tf32(acc[mt][nt], a[mt][0], a[mt][1], a[mt][2], a[mt][3],
                             bf[nt][0], bf[nt][1]);
        }
        __syncthreads();
    }

#pragma unroll
    for (int mt = 0; mt < 2; mt++)
#pragma unroll
        for (int nt = 0; nt < 2; nt++)
#pragma unroll
            for (int ri = 0; ri < 4; ri++) {
                int r = wm * 32 + mt * 16 + g + ((ri >= 2) ? 8 : 0);
                int c = wn * 16 + nt * 8 + 2 * t + (ri & 1);
                int qg = qt * 64 + r;
                ctx[((size_t)b * SS + qg) * HID + h * HD + c] = acc[mt][nt][ri];
            }
}

// ---------------------------------------------------------------------------
extern "C" void kernel_launch(void* const* d_in, const int* in_sizes, int n_in,
                              void* d_out, int out_size)
{
    const float* hidden = (const float*)d_in[0];
    const float* mask   = (const float*)d_in[1];
    const float* cosb   = (const float*)d_in[2];
    const float* sinb   = (const float*)d_in[3];
    const float* wq     = (const float*)d_in[4];
    const float* wk     = (const float*)d_in[5];
    const float* wv     = (const float*)d_in[6];
    const float* wo     = (const float*)d_in[7];

    float* outp = (float*)d_out;

    float *qp, *kp, *vp, *cp, *pp, *ip;
    cudaGetSymbolAddress((void**)&qp, g_q);
    cudaGetSymbolAddress((void**)&kp, g_k);
    cudaGetSymbolAddress((void**)&vp, g_v);
    cudaGetSymbolAddress((void**)&cp, g_ctx);
    cudaGetSymbolAddress((void**)&pp, g_part);
    cudaGetSymbolAddress((void**)&ip, g_inv);

    float* attnp;
    if ((size_t)out_size >= OUT_ELEMS + ATTN_ELEMS) {
        attnp = outp + OUT_ELEMS;
    } else {
        cudaGetSymbolAddress((void**)&attnp, g_attn_fallback);
    }

    // 1) fused QKV projection (cp.async pipelined tf32)
    qkv_kernel<<<dim3(24, 16), 256>>>(hidden, wq, wk, wv, qp, kp, vp);

    // 2) RoPE on q and k
    rope_kernel<<<(BB * NH * SS * 32) / 256, 256>>>(qp, BB * NH * SS, cosb, sinb);
    rope_kernel<<<(BB * NKV * SS * 32) / 256, 256>>>(kp, BB * NKV * SS, cosb, sinb);

    // 3) scores -> unnormalized exp + partial row sums
    scores_kernel<<<dim3(16, 16, BB * NH), 256>>>(qp, kp, mask, attnp, pp);

    // 4) combine partials -> 1/rowsum
    combine_kernel<<<NROWS / 256, 256>>>(pp, ip);

    // 5) ctx = attn @ V; normalizes attn in place (final output)
    ctx_kernel<<<dim3(1, 16, BB * NH), 256>>>(attnp, vp, ip, cp);

    // 6) out = ctx @ wo
    gemm_kernel<<<dim3(16, 16), 256>>>(cp, wo, outp, 2048, 2048, 2048);
}